// round 16
// baseline (speedup 1.0000x reference)
#include <cuda_runtime.h>
#include <cuda_bf16.h>
#include <cuda_fp16.h>
#include <math.h>

#define NN   100000
#define FIN  512
#define HC   64        // HEADS*HID
#define H    8
#define CLS  7
#define H2P  8         // padded h2 row stride
#define EMAX 1600000
#define LRELU 0.2f
#define NBLK 98        // ceil(NN/1024)

// ---------------- scratch (device globals; allocation-free) ----------------
__device__ __half2 g_h1[(size_t)NN * 32];  // layer1 linear output, fp16 (32 half2/row)
__device__ float g_as1[NN * H];
__device__ float g_ad1[NN * H];
__device__ float g_h2[NN * H2P];           // padded to 8 floats/row
__device__ float g_as2[NN];
__device__ float g_ad2[NN];
__device__ int   g_deg[NN];
__device__ int   g_off[NN + 1];
__device__ int   g_cur[NN];
__device__ int   g_srcs[EMAX];
__device__ int   g_bsum[128];
__device__ int   g_bcar[128];

__device__ __forceinline__ float lrelu(float x) { return x > 0.f ? x : LRELU * x; }

// ---------------- CSR build ----------------
__global__ void k_zero_deg() {
    int i = blockIdx.x * blockDim.x + threadIdx.x;
    if (i < NN) g_deg[i] = 0;
}

__global__ void k_hist(const int* __restrict__ dst, int E) {
    int i = blockIdx.x * blockDim.x + threadIdx.x;
    if (i < E) atomicAdd(&g_deg[dst[i]], 1);
}

__global__ void k_scan1() {
    __shared__ int wsum[32];
    int t = threadIdx.x;
    int i = blockIdx.x * 1024 + t;
    int lane = t & 31, wid = t >> 5;
    int v = (i < NN) ? g_deg[i] : 0;
    int s = v;
    #pragma unroll
    for (int off = 1; off < 32; off <<= 1) {
        int u = __shfl_up_sync(0xffffffffu, s, off);
        if (lane >= off) s += u;
    }
    if (lane == 31) wsum[wid] = s;
    __syncthreads();
    if (wid == 0) {
        int ws = wsum[lane];
        #pragma unroll
        for (int off = 1; off < 32; off <<= 1) {
            int u = __shfl_up_sync(0xffffffffu, ws, off);
            if (lane >= off) ws += u;
        }
        wsum[lane] = ws;
    }
    __syncthreads();
    int carry = (wid > 0) ? wsum[wid - 1] : 0;
    int incl = s + carry;
    if (i < NN) g_off[i] = incl - v;
    if (t == 1023) g_bsum[blockIdx.x] = incl;
}

__global__ void k_scan2() {
    __shared__ int ws[4];
    int t = threadIdx.x, lane = t & 31, wid = t >> 5;
    int v = (t < NBLK) ? g_bsum[t] : 0;
    int s = v;
    #pragma unroll
    for (int off = 1; off < 32; off <<= 1) {
        int u = __shfl_up_sync(0xffffffffu, s, off);
        if (lane >= off) s += u;
    }
    if (lane == 31) ws[wid] = s;
    __syncthreads();
    int carry = 0;
    for (int w = 0; w < wid; w++) carry += ws[w];
    int incl = s + carry;
    g_bcar[t] = incl - v;
    if (t == 127) g_off[NN] = incl;
}

__global__ void k_scan3() {
    int i = blockIdx.x * blockDim.x + threadIdx.x;
    if (i < NN) {
        int o = g_off[i] + g_bcar[i >> 10];
        g_off[i] = o;
        g_cur[i] = o;
    }
}

__global__ void k_scatter(const int* __restrict__ src, const int* __restrict__ dst, int E) {
    int i = blockIdx.x * blockDim.x + threadIdx.x;
    if (i < E) {
        int d = dst[i];
        int pos = atomicAdd(&g_cur[d], 1);
        g_srcs[pos] = src[i];
    }
}

// ---------------- layer 1 GEMM (tensor cores, split-bf16 x3) + fused alpha ----------------
// Block tile 128x64, 8 warps (256 thr), warp tile 32x32. Software-pipelined.

#define MMA_OP(d, a, b) asm volatile( \
    "mma.sync.aligned.m16n8k16.row.col.f32.bf16.bf16.f32 " \
    "{%0,%1,%2,%3}, {%4,%5,%6,%7}, {%8,%9}, {%0,%1,%2,%3};" \
    : "+f"(d[0]), "+f"(d[1]), "+f"(d[2]), "+f"(d[3]) \
    : "r"(a[0]), "r"(a[1]), "r"(a[2]), "r"(a[3]), "r"(b[0]), "r"(b[1]))

__global__ __launch_bounds__(256) void k_gemm1_tc(const float* __restrict__ x,
                                                  const float* __restrict__ W,
                                                  const float* __restrict__ a_src,
                                                  const float* __restrict__ a_dst) {
    __shared__ __align__(16) __nv_bfloat16 As_hi[128][40];  // 32 k + 8 pad
    __shared__ __align__(16) __nv_bfloat16 As_lo[128][40];
    __shared__ __align__(16) __nv_bfloat16 Bs_hi[32][72];   // 64 n + 8 pad
    __shared__ __align__(16) __nv_bfloat16 Bs_lo[32][72];

    int tid = threadIdx.x;
    int lane = tid & 31, wid = tid >> 5;
    int wm = wid & 3;          // warp m: 0..3 -> rows wm*32
    int wn = wid >> 2;         // warp n: 0..1 -> cols wn*32
    int row0 = blockIdx.x * 128;

    float acc[2][4][4];
    #pragma unroll
    for (int i = 0; i < 2; i++)
        #pragma unroll
        for (int j = 0; j < 4; j++)
            #pragma unroll
            for (int q = 0; q < 4; q++) acc[i][j][q] = 0.f;

    int arow = tid >> 1;
    int akq = (tid & 1) * 16;
    bool aok = (row0 + arow) < NN;
    const float* ap = x + (size_t)(row0 + arow) * FIN + akq;
    int bkr = tid >> 3;
    int bnq = (tid & 7) * 8;
    const float* bp = W + (size_t)bkr * HC + bnq;

    int lr = lane & 15;
    int lc8 = (lane >> 4) * 8;

    // ---- prologue: load k0 = 0 ----
    float va[16], vb[8];
    {
        if (aok) {
            float4 t0 = *(const float4*)(ap);
            float4 t1 = *(const float4*)(ap + 4);
            float4 t2 = *(const float4*)(ap + 8);
            float4 t3 = *(const float4*)(ap + 12);
            va[0]=t0.x; va[1]=t0.y; va[2]=t0.z; va[3]=t0.w;
            va[4]=t1.x; va[5]=t1.y; va[6]=t1.z; va[7]=t1.w;
            va[8]=t2.x; va[9]=t2.y; va[10]=t2.z; va[11]=t2.w;
            va[12]=t3.x; va[13]=t3.y; va[14]=t3.z; va[15]=t3.w;
        } else {
            #pragma unroll
            for (int e = 0; e < 16; e++) va[e] = 0.f;
        }
        float4 t0 = *(const float4*)(bp);
        float4 t1 = *(const float4*)(bp + 4);
        vb[0]=t0.x; vb[1]=t0.y; vb[2]=t0.z; vb[3]=t0.w;
        vb[4]=t1.x; vb[5]=t1.y; vb[6]=t1.z; vb[7]=t1.w;
    }

    for (int k0 = 0; k0 < FIN; k0 += 32) {
        __nv_bfloat16 ah16[16], al16[16];
        #pragma unroll
        for (int e = 0; e < 16; e++) {
            __nv_bfloat16 hv = __float2bfloat16(va[e]);
            ah16[e] = hv;
            al16[e] = __float2bfloat16(va[e] - __bfloat162float(hv));
        }
        __nv_bfloat16 bh16[8], bl16[8];
        #pragma unroll
        for (int e = 0; e < 8; e++) {
            __nv_bfloat16 hv = __float2bfloat16(vb[e]);
            bh16[e] = hv;
            bl16[e] = __float2bfloat16(vb[e] - __bfloat162float(hv));
        }

        __syncthreads();
        *(uint4*)&As_hi[arow][akq]     = *(uint4*)&ah16[0];
        *(uint4*)&As_hi[arow][akq + 8] = *(uint4*)&ah16[8];
        *(uint4*)&As_lo[arow][akq]     = *(uint4*)&al16[0];
        *(uint4*)&As_lo[arow][akq + 8] = *(uint4*)&al16[8];
        *(uint4*)&Bs_hi[bkr][bnq] = *(uint4*)&bh16[0];
        *(uint4*)&Bs_lo[bkr][bnq] = *(uint4*)&bl16[0];
        __syncthreads();

        if (k0 + 32 < FIN) {
            if (aok) {
                float4 t0 = *(const float4*)(ap + k0 + 32);
                float4 t1 = *(const float4*)(ap + k0 + 36);
                float4 t2 = *(const float4*)(ap + k0 + 40);
                float4 t3 = *(const float4*)(ap + k0 + 44);
                va[0]=t0.x; va[1]=t0.y; va[2]=t0.z; va[3]=t0.w;
                va[4]=t1.x; va[5]=t1.y; va[6]=t1.z; va[7]=t1.w;
                va[8]=t2.x; va[9]=t2.y; va[10]=t2.z; va[11]=t2.w;
                va[12]=t3.x; va[13]=t3.y; va[14]=t3.z; va[15]=t3.w;
            }
            const float* wp = bp + (size_t)(k0 + 32) * HC;
            float4 t0 = *(const float4*)(wp);
            float4 t1 = *(const float4*)(wp + 4);
            vb[0]=t0.x; vb[1]=t0.y; vb[2]=t0.z; vb[3]=t0.w;
            vb[4]=t1.x; vb[5]=t1.y; vb[6]=t1.z; vb[7]=t1.w;
        }

        #pragma unroll
        for (int kk = 0; kk < 32; kk += 16) {
            unsigned ah[2][4], al[2][4];
            #pragma unroll
            for (int im = 0; im < 2; im++) {
                unsigned addr_h = (unsigned)__cvta_generic_to_shared(
                    &As_hi[wm * 32 + im * 16 + lr][kk + lc8]);
                asm volatile("ldmatrix.sync.aligned.m8n8.x4.shared.b16 {%0,%1,%2,%3}, [%4];"
                    : "=r"(ah[im][0]), "=r"(ah[im][1]), "=r"(ah[im][2]), "=r"(ah[im][3])
                    : "r"(addr_h));
                unsigned addr_l = (unsigned)__cvta_generic_to_shared(
                    &As_lo[wm * 32 + im * 16 + lr][kk + lc8]);
                asm volatile("ldmatrix.sync.aligned.m8n8.x4.shared.b16 {%0,%1,%2,%3}, [%4];"
                    : "=r"(al[im][0]), "=r"(al[im][1]), "=r"(al[im][2]), "=r"(al[im][3])
                    : "r"(addr_l));
            }
            unsigned bh[4][2], bl[4][2];
            #pragma unroll
            for (int nh = 0; nh < 2; nh++) {
                unsigned r0, r1, r2, r3;
                unsigned addr_h = (unsigned)__cvta_generic_to_shared(
                    &Bs_hi[kk + lr][wn * 32 + nh * 16 + lc8]);
                asm volatile("ldmatrix.sync.aligned.m8n8.x4.trans.shared.b16 {%0,%1,%2,%3}, [%4];"
                    : "=r"(r0), "=r"(r1), "=r"(r2), "=r"(r3) : "r"(addr_h));
                bh[nh * 2 + 0][0] = r0; bh[nh * 2 + 0][1] = r1;
                bh[nh * 2 + 1][0] = r2; bh[nh * 2 + 1][1] = r3;
                unsigned addr_l = (unsigned)__cvta_generic_to_shared(
                    &Bs_lo[kk + lr][wn * 32 + nh * 16 + lc8]);
                asm volatile("ldmatrix.sync.aligned.m8n8.x4.trans.shared.b16 {%0,%1,%2,%3}, [%4];"
                    : "=r"(r0), "=r"(r1), "=r"(r2), "=r"(r3) : "r"(addr_l));
                bl[nh * 2 + 0][0] = r0; bl[nh * 2 + 0][1] = r1;
                bl[nh * 2 + 1][0] = r2; bl[nh * 2 + 1][1] = r3;
            }
            #pragma unroll
            for (int im = 0; im < 2; im++) {
                #pragma unroll
                for (int in = 0; in < 4; in++) {
                    MMA_OP(acc[im][in], ah[im], bh[in]);
                    MMA_OP(acc[im][in], ah[im], bl[in]);
                    MMA_OP(acc[im][in], al[im], bh[in]);
                }
            }
        }
    }

    // ---- epilogue: h1 stores (fp16) + fused alpha from fp32 acc ----
    int r = lane >> 2;
    int cq = (lane & 3) * 2;
    float asw[4][2], adw[4][2];
    #pragma unroll
    for (int in = 0; in < 4; in++) {
        int c = wn * 32 + in * 8 + cq;
        asw[in][0] = __ldg(&a_src[c]);     asw[in][1] = __ldg(&a_src[c + 1]);
        adw[in][0] = __ldg(&a_dst[c]);     adw[in][1] = __ldg(&a_dst[c + 1]);
    }
    #pragma unroll
    for (int im = 0; im < 2; im++) {
        int mlo = row0 + wm * 32 + im * 16 + r;
        int mhi = mlo + 8;
        #pragma unroll
        for (int in = 0; in < 4; in++) {
            int hcol = wn * 16 + in * 4 + (lane & 3);   // half2 index within row
            if (mlo < NN)
                g_h1[(size_t)mlo * 32 + hcol] =
                    __floats2half2_rn(acc[im][in][0], acc[im][in][1]);
            if (mhi < NN)
                g_h1[(size_t)mhi * 32 + hcol] =
                    __floats2half2_rn(acc[im][in][2], acc[im][in][3]);
            int hd = wn * 4 + in;
            float slo = acc[im][in][0]*asw[in][0] + acc[im][in][1]*asw[in][1];
            float dlo = acc[im][in][0]*adw[in][0] + acc[im][in][1]*adw[in][1];
            float shi = acc[im][in][2]*asw[in][0] + acc[im][in][3]*asw[in][1];
            float dhi = acc[im][in][2]*adw[in][0] + acc[im][in][3]*adw[in][1];
            slo += __shfl_xor_sync(0xffffffffu, slo, 1);
            slo += __shfl_xor_sync(0xffffffffu, slo, 2);
            dlo += __shfl_xor_sync(0xffffffffu, dlo, 1);
            dlo += __shfl_xor_sync(0xffffffffu, dlo, 2);
            shi += __shfl_xor_sync(0xffffffffu, shi, 1);
            shi += __shfl_xor_sync(0xffffffffu, shi, 2);
            dhi += __shfl_xor_sync(0xffffffffu, dhi, 1);
            dhi += __shfl_xor_sync(0xffffffffu, dhi, 2);
            if ((lane & 3) == 0) {
                if (mlo < NN) { g_as1[mlo * H + hd] = slo; g_ad1[mlo * H + hd] = dlo; }
                if (mhi < NN) { g_as1[mhi * H + hd] = shi; g_ad1[mhi * H + hd] = dhi; }
            }
        }
    }
}

// ---------------- fused layer-1 aggregation (fp16 h1) + layer-2 linear + alpha2 ----------------
__global__ void k_agg1(const float* __restrict__ b1, const float* __restrict__ W2,
                       const float* __restrict__ a_s2, const float* __restrict__ a_d2) {
    int warp = (blockIdx.x * blockDim.x + threadIdx.x) >> 5;
    if (warp >= NN) return;
    int lane = threadIdx.x & 31;
    int n = warp;
    int h2 = lane >> 2;                          // head of my 2 channels
    float ad = __ldg(&g_ad1[n * H + h2]);
    float p0 = __expf(lrelu(__ldg(&g_as1[n * H + h2]) + ad));  // self loop
    float den = p0;
    float2 hv = __half22float2(g_h1[(size_t)n * 32 + lane]);
    float ax = p0 * hv.x, ay = p0 * hv.y;
    int beg = g_off[n], end = g_off[n + 1];
    #pragma unroll 2
    for (int i = beg; i < end; ++i) {
        int s = g_srcs[i];
        float p = __expf(lrelu(__ldg(&g_as1[s * H + h2]) + ad));
        den += p;
        float2 v = __half22float2(g_h1[(size_t)s * 32 + lane]);
        ax = fmaf(p, v.x, ax);
        ay = fmaf(p, v.y, ay);
    }
    float inv = 1.0f / den;
    float o0 = fmaf(ax, inv, __ldg(&b1[2 * lane]));
    float o1 = fmaf(ay, inv, __ldg(&b1[2 * lane + 1]));
    o0 = o0 > 0.f ? o0 : __expf(o0) - 1.f;       // ELU
    o1 = o1 > 0.f ? o1 : __expf(o1) - 1.f;

    // ---- fused layer-2 linear: h2[c] = sum_k x2[k] * W2[k][c] ----
    const float* w2a = W2 + (2 * lane) * CLS;
    const float* w2b = W2 + (2 * lane + 1) * CLS;
    float hp[CLS];
    #pragma unroll
    for (int c = 0; c < CLS; c++)
        hp[c] = o0 * __ldg(&w2a[c]) + o1 * __ldg(&w2b[c]);
    #pragma unroll
    for (int off = 16; off >= 1; off >>= 1) {
        #pragma unroll
        for (int c = 0; c < CLS; c++)
            hp[c] += __shfl_xor_sync(0xffffffffu, hp[c], off);
    }
    if (lane == 0) {
        float as = 0.f, adv = 0.f;
        #pragma unroll
        for (int c = 0; c < CLS; c++) {
            as  = fmaf(hp[c], __ldg(&a_s2[c]), as);
            adv = fmaf(hp[c], __ldg(&a_d2[c]), adv);
        }
        *(float4*)&g_h2[n * H2P]     = make_float4(hp[0], hp[1], hp[2], hp[3]);
        *(float4*)&g_h2[n * H2P + 4] = make_float4(hp[4], hp[5], hp[6], 0.f);
        g_as2[n] = as;
        g_ad2[n] = adv;
    }
}

// ---------------- layer 2 aggregation: warp per node, lane per edge ----------------
__global__ void k_agg2(const float* __restrict__ b2, float* __restrict__ out) {
    int warp = (blockIdx.x * blockDim.x + threadIdx.x) >> 5;
    if (warp >= NN) return;
    int lane = threadIdx.x & 31;
    int n = warp;
    float adv = g_ad2[n];
    float den = 0.f;
    float acc[CLS] = {};
    int beg = g_off[n], end = g_off[n + 1];
    for (int i = beg + lane; i < end; i += 32) {
        int s = g_srcs[i];
        float p = __expf(lrelu(__ldg(&g_as2[s]) + adv));
        den += p;
        float4 v0 = *(const float4*)&g_h2[s * H2P];
        float4 v1 = *(const float4*)&g_h2[s * H2P + 4];
        acc[0] = fmaf(p, v0.x, acc[0]);
        acc[1] = fmaf(p, v0.y, acc[1]);
        acc[2] = fmaf(p, v0.z, acc[2]);
        acc[3] = fmaf(p, v0.w, acc[3]);
        acc[4] = fmaf(p, v1.x, acc[4]);
        acc[5] = fmaf(p, v1.y, acc[5]);
        acc[6] = fmaf(p, v1.z, acc[6]);
    }
    if (lane == 0) {   // self loop
        float p0 = __expf(lrelu(g_as2[n] + adv));
        den += p0;
        float4 s0 = *(const float4*)&g_h2[n * H2P];
        float4 s1 = *(const float4*)&g_h2[n * H2P + 4];
        acc[0] = fmaf(p0, s0.x, acc[0]);
        acc[1] = fmaf(p0, s0.y, acc[1]);
        acc[2] = fmaf(p0, s0.z, acc[2]);
        acc[3] = fmaf(p0, s0.w, acc[3]);
        acc[4] = fmaf(p0, s1.x, acc[4]);
        acc[5] = fmaf(p0, s1.y, acc[5]);
        acc[6] = fmaf(p0, s1.z, acc[6]);
    }
    // butterfly reduce den + acc[0..6] across the warp
    #pragma unroll
    for (int off = 16; off >= 1; off >>= 1) {
        den += __shfl_xor_sync(0xffffffffu, den, off);
        #pragma unroll
        for (int c = 0; c < CLS; c++)
            acc[c] += __shfl_xor_sync(0xffffffffu, acc[c], off);
    }
    float inv = 1.0f / den;
    float o[CLS];
    #pragma unroll
    for (int c = 0; c < CLS; c++) o[c] = fmaf(acc[c], inv, __ldg(&b2[c]));
    float mx = o[0];
    #pragma unroll
    for (int c = 1; c < CLS; c++) mx = fmaxf(mx, o[c]);
    float ssum = 0.f;
    #pragma unroll
    for (int c = 0; c < CLS; c++) ssum += __expf(o[c] - mx);
    float lse = __logf(ssum);
    if (lane < CLS)
        out[n * CLS + lane] = o[lane] - mx - lse;
}

// ---------------- launch (CSR chain overlapped with GEMM on a side stream) ----------------
extern "C" void kernel_launch(void* const* d_in, const int* in_sizes, int n_in,
                              void* d_out, int out_size) {
    const float* x     = (const float*)d_in[0];
    const int*   ei    = (const int*)  d_in[1];
    const float* W1    = (const float*)d_in[2];
    const float* as1   = (const float*)d_in[3];
    const float* ad1   = (const float*)d_in[4];
    const float* b1    = (const float*)d_in[5];
    const float* W2    = (const float*)d_in[6];
    const float* as2   = (const float*)d_in[7];
    const float* ad2   = (const float*)d_in[8];
    const float* b2    = (const float*)d_in[9];
    float* out = (float*)d_out;

    int E = in_sizes[1] / 2;
    const int* src = ei;
    const int* dst = ei + E;
    int eb = (E + 255) / 256;

    static cudaStream_t sA = nullptr;
    static cudaEvent_t eFork = nullptr, eJoin = nullptr;
    if (sA == nullptr) {
        cudaStreamCreateWithFlags(&sA, cudaStreamNonBlocking);
        cudaEventCreateWithFlags(&eFork, cudaEventDisableTiming);
        cudaEventCreateWithFlags(&eJoin, cudaEventDisableTiming);
    }

    // fork: side stream joins the capture graph
    cudaEventRecord(eFork, 0);
    cudaStreamWaitEvent(sA, eFork, 0);

    // CSR chain on side stream, GEMM on main (launch 4 = ncu slot)
    k_zero_deg<<<(NN + 255) / 256, 256, 0, sA>>>();                 // 1
    k_hist<<<eb, 256, 0, sA>>>(dst, E);                             // 2
    k_scan1<<<NBLK, 1024, 0, sA>>>();                               // 3
    k_gemm1_tc<<<(NN + 127) / 128, 256>>>(x, W1, as1, ad1);         // 4 <- profiled
    k_scan2<<<1, 128, 0, sA>>>();                                   // 5
    k_scan3<<<(NN + 255) / 256, 256, 0, sA>>>();                    // 6
    k_scatter<<<eb, 256, 0, sA>>>(src, dst, E);                     // 7

    // join: main stream waits for CSR completion
    cudaEventRecord(eJoin, sA);
    cudaStreamWaitEvent(0, eJoin, 0);

    k_agg1<<<(NN * 32 + 255) / 256, 256>>>(b1, W2, as2, ad2);       // 8 (fused lin2)
    k_agg2<<<(NN * 32 + 255) / 256, 256>>>(b2, out);                // 9 (warp per node)
}

// round 17
// speedup vs baseline: 1.0869x; 1.0869x over previous
#include <cuda_runtime.h>
#include <cuda_bf16.h>
#include <cuda_fp16.h>
#include <math.h>

#define NN   100000
#define FIN  512
#define HC   64        // HEADS*HID
#define H    8
#define CLS  7
#define H2P  8         // padded h2 row stride
#define EMAX 1600000
#define LRELU 0.2f
#define NBLK 98        // ceil(NN/1024)

// ---------------- scratch (device globals; allocation-free) ----------------
__device__ __half2 g_h1[(size_t)NN * 32];  // layer1 linear output, fp16 (32 half2/row)
__device__ float g_as1[NN * H];
__device__ float g_ad1[NN * H];
__device__ float g_h2[NN * H2P];           // padded to 8 floats/row
__device__ float g_as2[NN];
__device__ float g_ad2[NN];
__device__ int   g_deg[NN];
__device__ int   g_off[NN + 1];
__device__ int   g_cur[NN];
__device__ int   g_srcs[EMAX];
__device__ int   g_bsum[128];
__device__ int   g_bcar[128];

__device__ __forceinline__ float lrelu(float x) { return x > 0.f ? x : LRELU * x; }

// ---------------- CSR build ----------------
__global__ void k_zero_deg() {
    int i = blockIdx.x * blockDim.x + threadIdx.x;
    if (i < NN) g_deg[i] = 0;
}

__global__ void k_hist(const int* __restrict__ dst, int E) {
    int i = blockIdx.x * blockDim.x + threadIdx.x;
    if (i < E) atomicAdd(&g_deg[dst[i]], 1);
}

__global__ void k_scan1() {
    __shared__ int wsum[32];
    int t = threadIdx.x;
    int i = blockIdx.x * 1024 + t;
    int lane = t & 31, wid = t >> 5;
    int v = (i < NN) ? g_deg[i] : 0;
    int s = v;
    #pragma unroll
    for (int off = 1; off < 32; off <<= 1) {
        int u = __shfl_up_sync(0xffffffffu, s, off);
        if (lane >= off) s += u;
    }
    if (lane == 31) wsum[wid] = s;
    __syncthreads();
    if (wid == 0) {
        int ws = wsum[lane];
        #pragma unroll
        for (int off = 1; off < 32; off <<= 1) {
            int u = __shfl_up_sync(0xffffffffu, ws, off);
            if (lane >= off) ws += u;
        }
        wsum[lane] = ws;
    }
    __syncthreads();
    int carry = (wid > 0) ? wsum[wid - 1] : 0;
    int incl = s + carry;
    if (i < NN) g_off[i] = incl - v;
    if (t == 1023) g_bsum[blockIdx.x] = incl;
}

__global__ void k_scan2() {
    __shared__ int ws[4];
    int t = threadIdx.x, lane = t & 31, wid = t >> 5;
    int v = (t < NBLK) ? g_bsum[t] : 0;
    int s = v;
    #pragma unroll
    for (int off = 1; off < 32; off <<= 1) {
        int u = __shfl_up_sync(0xffffffffu, s, off);
        if (lane >= off) s += u;
    }
    if (lane == 31) ws[wid] = s;
    __syncthreads();
    int carry = 0;
    for (int w = 0; w < wid; w++) carry += ws[w];
    int incl = s + carry;
    g_bcar[t] = incl - v;
    if (t == 127) g_off[NN] = incl;
}

__global__ void k_scan3() {
    int i = blockIdx.x * blockDim.x + threadIdx.x;
    if (i < NN) {
        int o = g_off[i] + g_bcar[i >> 10];
        g_off[i] = o;
        g_cur[i] = o;
    }
}

__global__ void k_scatter(const int* __restrict__ src, const int* __restrict__ dst, int E) {
    int i = blockIdx.x * blockDim.x + threadIdx.x;
    if (i < E) {
        int d = dst[i];
        int pos = atomicAdd(&g_cur[d], 1);
        g_srcs[pos] = src[i];
    }
}

// ---------------- layer 1 GEMM (tensor cores, split-bf16 x3) + fused alpha ----------------
// Block tile 128x64, 8 warps (256 thr), warp tile 32x32. Software-pipelined.

#define MMA_OP(d, a, b) asm volatile( \
    "mma.sync.aligned.m16n8k16.row.col.f32.bf16.bf16.f32 " \
    "{%0,%1,%2,%3}, {%4,%5,%6,%7}, {%8,%9}, {%0,%1,%2,%3};" \
    : "+f"(d[0]), "+f"(d[1]), "+f"(d[2]), "+f"(d[3]) \
    : "r"(a[0]), "r"(a[1]), "r"(a[2]), "r"(a[3]), "r"(b[0]), "r"(b[1]))

__global__ __launch_bounds__(256) void k_gemm1_tc(const float* __restrict__ x,
                                                  const float* __restrict__ W,
                                                  const float* __restrict__ a_src,
                                                  const float* __restrict__ a_dst) {
    __shared__ __align__(16) __nv_bfloat16 As_hi[128][40];  // 32 k + 8 pad
    __shared__ __align__(16) __nv_bfloat16 As_lo[128][40];
    __shared__ __align__(16) __nv_bfloat16 Bs_hi[32][72];   // 64 n + 8 pad
    __shared__ __align__(16) __nv_bfloat16 Bs_lo[32][72];

    int tid = threadIdx.x;
    int lane = tid & 31, wid = tid >> 5;
    int wm = wid & 3;          // warp m: 0..3 -> rows wm*32
    int wn = wid >> 2;         // warp n: 0..1 -> cols wn*32
    int row0 = blockIdx.x * 128;

    float acc[2][4][4];
    #pragma unroll
    for (int i = 0; i < 2; i++)
        #pragma unroll
        for (int j = 0; j < 4; j++)
            #pragma unroll
            for (int q = 0; q < 4; q++) acc[i][j][q] = 0.f;

    int arow = tid >> 1;
    int akq = (tid & 1) * 16;
    bool aok = (row0 + arow) < NN;
    const float* ap = x + (size_t)(row0 + arow) * FIN + akq;
    int bkr = tid >> 3;
    int bnq = (tid & 7) * 8;
    const float* bp = W + (size_t)bkr * HC + bnq;

    int lr = lane & 15;
    int lc8 = (lane >> 4) * 8;

    // ---- prologue: load k0 = 0 ----
    float va[16], vb[8];
    {
        if (aok) {
            float4 t0 = *(const float4*)(ap);
            float4 t1 = *(const float4*)(ap + 4);
            float4 t2 = *(const float4*)(ap + 8);
            float4 t3 = *(const float4*)(ap + 12);
            va[0]=t0.x; va[1]=t0.y; va[2]=t0.z; va[3]=t0.w;
            va[4]=t1.x; va[5]=t1.y; va[6]=t1.z; va[7]=t1.w;
            va[8]=t2.x; va[9]=t2.y; va[10]=t2.z; va[11]=t2.w;
            va[12]=t3.x; va[13]=t3.y; va[14]=t3.z; va[15]=t3.w;
        } else {
            #pragma unroll
            for (int e = 0; e < 16; e++) va[e] = 0.f;
        }
        float4 t0 = *(const float4*)(bp);
        float4 t1 = *(const float4*)(bp + 4);
        vb[0]=t0.x; vb[1]=t0.y; vb[2]=t0.z; vb[3]=t0.w;
        vb[4]=t1.x; vb[5]=t1.y; vb[6]=t1.z; vb[7]=t1.w;
    }

    for (int k0 = 0; k0 < FIN; k0 += 32) {
        __nv_bfloat16 ah16[16], al16[16];
        #pragma unroll
        for (int e = 0; e < 16; e++) {
            __nv_bfloat16 hv = __float2bfloat16(va[e]);
            ah16[e] = hv;
            al16[e] = __float2bfloat16(va[e] - __bfloat162float(hv));
        }
        __nv_bfloat16 bh16[8], bl16[8];
        #pragma unroll
        for (int e = 0; e < 8; e++) {
            __nv_bfloat16 hv = __float2bfloat16(vb[e]);
            bh16[e] = hv;
            bl16[e] = __float2bfloat16(vb[e] - __bfloat162float(hv));
        }

        __syncthreads();
        *(uint4*)&As_hi[arow][akq]     = *(uint4*)&ah16[0];
        *(uint4*)&As_hi[arow][akq + 8] = *(uint4*)&ah16[8];
        *(uint4*)&As_lo[arow][akq]     = *(uint4*)&al16[0];
        *(uint4*)&As_lo[arow][akq + 8] = *(uint4*)&al16[8];
        *(uint4*)&Bs_hi[bkr][bnq] = *(uint4*)&bh16[0];
        *(uint4*)&Bs_lo[bkr][bnq] = *(uint4*)&bl16[0];
        __syncthreads();

        if (k0 + 32 < FIN) {
            if (aok) {
                float4 t0 = *(const float4*)(ap + k0 + 32);
                float4 t1 = *(const float4*)(ap + k0 + 36);
                float4 t2 = *(const float4*)(ap + k0 + 40);
                float4 t3 = *(const float4*)(ap + k0 + 44);
                va[0]=t0.x; va[1]=t0.y; va[2]=t0.z; va[3]=t0.w;
                va[4]=t1.x; va[5]=t1.y; va[6]=t1.z; va[7]=t1.w;
                va[8]=t2.x; va[9]=t2.y; va[10]=t2.z; va[11]=t2.w;
                va[12]=t3.x; va[13]=t3.y; va[14]=t3.z; va[15]=t3.w;
            }
            const float* wp = bp + (size_t)(k0 + 32) * HC;
            float4 t0 = *(const float4*)(wp);
            float4 t1 = *(const float4*)(wp + 4);
            vb[0]=t0.x; vb[1]=t0.y; vb[2]=t0.z; vb[3]=t0.w;
            vb[4]=t1.x; vb[5]=t1.y; vb[6]=t1.z; vb[7]=t1.w;
        }

        #pragma unroll
        for (int kk = 0; kk < 32; kk += 16) {
            unsigned ah[2][4], al[2][4];
            #pragma unroll
            for (int im = 0; im < 2; im++) {
                unsigned addr_h = (unsigned)__cvta_generic_to_shared(
                    &As_hi[wm * 32 + im * 16 + lr][kk + lc8]);
                asm volatile("ldmatrix.sync.aligned.m8n8.x4.shared.b16 {%0,%1,%2,%3}, [%4];"
                    : "=r"(ah[im][0]), "=r"(ah[im][1]), "=r"(ah[im][2]), "=r"(ah[im][3])
                    : "r"(addr_h));
                unsigned addr_l = (unsigned)__cvta_generic_to_shared(
                    &As_lo[wm * 32 + im * 16 + lr][kk + lc8]);
                asm volatile("ldmatrix.sync.aligned.m8n8.x4.shared.b16 {%0,%1,%2,%3}, [%4];"
                    : "=r"(al[im][0]), "=r"(al[im][1]), "=r"(al[im][2]), "=r"(al[im][3])
                    : "r"(addr_l));
            }
            unsigned bh[4][2], bl[4][2];
            #pragma unroll
            for (int nh = 0; nh < 2; nh++) {
                unsigned r0, r1, r2, r3;
                unsigned addr_h = (unsigned)__cvta_generic_to_shared(
                    &Bs_hi[kk + lr][wn * 32 + nh * 16 + lc8]);
                asm volatile("ldmatrix.sync.aligned.m8n8.x4.trans.shared.b16 {%0,%1,%2,%3}, [%4];"
                    : "=r"(r0), "=r"(r1), "=r"(r2), "=r"(r3) : "r"(addr_h));
                bh[nh * 2 + 0][0] = r0; bh[nh * 2 + 0][1] = r1;
                bh[nh * 2 + 1][0] = r2; bh[nh * 2 + 1][1] = r3;
                unsigned addr_l = (unsigned)__cvta_generic_to_shared(
                    &Bs_lo[kk + lr][wn * 32 + nh * 16 + lc8]);
                asm volatile("ldmatrix.sync.aligned.m8n8.x4.trans.shared.b16 {%0,%1,%2,%3}, [%4];"
                    : "=r"(r0), "=r"(r1), "=r"(r2), "=r"(r3) : "r"(addr_l));
                bl[nh * 2 + 0][0] = r0; bl[nh * 2 + 0][1] = r1;
                bl[nh * 2 + 1][0] = r2; bl[nh * 2 + 1][1] = r3;
            }
            #pragma unroll
            for (int im = 0; im < 2; im++) {
                #pragma unroll
                for (int in = 0; in < 4; in++) {
                    MMA_OP(acc[im][in], ah[im], bh[in]);
                    MMA_OP(acc[im][in], ah[im], bl[in]);
                    MMA_OP(acc[im][in], al[im], bh[in]);
                }
            }
        }
    }

    // ---- epilogue: h1 stores (fp16) + fused alpha from fp32 acc ----
    int r = lane >> 2;
    int cq = (lane & 3) * 2;
    float asw[4][2], adw[4][2];
    #pragma unroll
    for (int in = 0; in < 4; in++) {
        int c = wn * 32 + in * 8 + cq;
        asw[in][0] = __ldg(&a_src[c]);     asw[in][1] = __ldg(&a_src[c + 1]);
        adw[in][0] = __ldg(&a_dst[c]);     adw[in][1] = __ldg(&a_dst[c + 1]);
    }
    #pragma unroll
    for (int im = 0; im < 2; im++) {
        int mlo = row0 + wm * 32 + im * 16 + r;
        int mhi = mlo + 8;
        #pragma unroll
        for (int in = 0; in < 4; in++) {
            int hcol = wn * 16 + in * 4 + (lane & 3);   // half2 index within row
            if (mlo < NN)
                g_h1[(size_t)mlo * 32 + hcol] =
                    __floats2half2_rn(acc[im][in][0], acc[im][in][1]);
            if (mhi < NN)
                g_h1[(size_t)mhi * 32 + hcol] =
                    __floats2half2_rn(acc[im][in][2], acc[im][in][3]);
            int hd = wn * 4 + in;
            float slo = acc[im][in][0]*asw[in][0] + acc[im][in][1]*asw[in][1];
            float dlo = acc[im][in][0]*adw[in][0] + acc[im][in][1]*adw[in][1];
            float shi = acc[im][in][2]*asw[in][0] + acc[im][in][3]*asw[in][1];
            float dhi = acc[im][in][2]*adw[in][0] + acc[im][in][3]*adw[in][1];
            slo += __shfl_xor_sync(0xffffffffu, slo, 1);
            slo += __shfl_xor_sync(0xffffffffu, slo, 2);
            dlo += __shfl_xor_sync(0xffffffffu, dlo, 1);
            dlo += __shfl_xor_sync(0xffffffffu, dlo, 2);
            shi += __shfl_xor_sync(0xffffffffu, shi, 1);
            shi += __shfl_xor_sync(0xffffffffu, shi, 2);
            dhi += __shfl_xor_sync(0xffffffffu, dhi, 1);
            dhi += __shfl_xor_sync(0xffffffffu, dhi, 2);
            if ((lane & 3) == 0) {
                if (mlo < NN) { g_as1[mlo * H + hd] = slo; g_ad1[mlo * H + hd] = dlo; }
                if (mhi < NN) { g_as1[mhi * H + hd] = shi; g_ad1[mhi * H + hd] = dhi; }
            }
        }
    }
}

// ---------------- fused layer-1 aggregation (fp16 h1) + layer-2 linear + alpha2 ----------------
// warp per node; edge loop manually pipelined 4-deep for MLP on the L2 chains.
__global__ void k_agg1(const float* __restrict__ b1, const float* __restrict__ W2,
                       const float* __restrict__ a_s2, const float* __restrict__ a_d2) {
    int warp = (blockIdx.x * blockDim.x + threadIdx.x) >> 5;
    if (warp >= NN) return;
    int lane = threadIdx.x & 31;
    int n = warp;
    int h2 = lane >> 2;                          // head of my 2 channels
    float ad = __ldg(&g_ad1[n * H + h2]);
    float p0 = __expf(lrelu(__ldg(&g_as1[n * H + h2]) + ad));  // self loop
    float den = p0;
    float2 hv = __half22float2(g_h1[(size_t)n * 32 + lane]);
    float ax = p0 * hv.x, ay = p0 * hv.y;
    int beg = g_off[n], end = g_off[n + 1];

    int i = beg;
    for (; i + 4 <= end; i += 4) {
        // phase 1: all indices
        int s0 = g_srcs[i], s1 = g_srcs[i + 1], s2 = g_srcs[i + 2], s3 = g_srcs[i + 3];
        // phase 2: all score + row loads (8 independent L2 accesses in flight)
        float e0 = __ldg(&g_as1[s0 * H + h2]);
        float e1 = __ldg(&g_as1[s1 * H + h2]);
        float e2 = __ldg(&g_as1[s2 * H + h2]);
        float e3 = __ldg(&g_as1[s3 * H + h2]);
        __half2 r0 = g_h1[(size_t)s0 * 32 + lane];
        __half2 r1 = g_h1[(size_t)s1 * 32 + lane];
        __half2 r2 = g_h1[(size_t)s2 * 32 + lane];
        __half2 r3 = g_h1[(size_t)s3 * 32 + lane];
        // phase 3: compute
        float q0 = __expf(lrelu(e0 + ad));
        float q1 = __expf(lrelu(e1 + ad));
        float q2 = __expf(lrelu(e2 + ad));
        float q3 = __expf(lrelu(e3 + ad));
        den += (q0 + q1) + (q2 + q3);
        float2 v0 = __half22float2(r0), v1 = __half22float2(r1);
        float2 v2 = __half22float2(r2), v3 = __half22float2(r3);
        ax = fmaf(q0, v0.x, ax); ay = fmaf(q0, v0.y, ay);
        ax = fmaf(q1, v1.x, ax); ay = fmaf(q1, v1.y, ay);
        ax = fmaf(q2, v2.x, ax); ay = fmaf(q2, v2.y, ay);
        ax = fmaf(q3, v3.x, ax); ay = fmaf(q3, v3.y, ay);
    }
    for (; i < end; ++i) {
        int s = g_srcs[i];
        float p = __expf(lrelu(__ldg(&g_as1[s * H + h2]) + ad));
        den += p;
        float2 v = __half22float2(g_h1[(size_t)s * 32 + lane]);
        ax = fmaf(p, v.x, ax);
        ay = fmaf(p, v.y, ay);
    }

    float inv = 1.0f / den;
    float o0 = fmaf(ax, inv, __ldg(&b1[2 * lane]));
    float o1 = fmaf(ay, inv, __ldg(&b1[2 * lane + 1]));
    o0 = o0 > 0.f ? o0 : __expf(o0) - 1.f;       // ELU
    o1 = o1 > 0.f ? o1 : __expf(o1) - 1.f;

    // ---- fused layer-2 linear: h2[c] = sum_k x2[k] * W2[k][c] ----
    const float* w2a = W2 + (2 * lane) * CLS;
    const float* w2b = W2 + (2 * lane + 1) * CLS;
    float hp[CLS];
    #pragma unroll
    for (int c = 0; c < CLS; c++)
        hp[c] = o0 * __ldg(&w2a[c]) + o1 * __ldg(&w2b[c]);
    #pragma unroll
    for (int off = 16; off >= 1; off >>= 1) {
        #pragma unroll
        for (int c = 0; c < CLS; c++)
            hp[c] += __shfl_xor_sync(0xffffffffu, hp[c], off);
    }
    if (lane == 0) {
        float as = 0.f, adv = 0.f;
        #pragma unroll
        for (int c = 0; c < CLS; c++) {
            as  = fmaf(hp[c], __ldg(&a_s2[c]), as);
            adv = fmaf(hp[c], __ldg(&a_d2[c]), adv);
        }
        *(float4*)&g_h2[n * H2P]     = make_float4(hp[0], hp[1], hp[2], hp[3]);
        *(float4*)&g_h2[n * H2P + 4] = make_float4(hp[4], hp[5], hp[6], 0.f);
        g_as2[n] = as;
        g_ad2[n] = adv;
    }
}

// ---------------- layer 2 aggregation: thread per node, manually pipelined x4 ----------------
__global__ void k_agg2(const float* __restrict__ b2, float* __restrict__ out) {
    int n = blockIdx.x * blockDim.x + threadIdx.x;
    if (n >= NN) return;
    float adv = g_ad2[n];
    float p0 = __expf(lrelu(g_as2[n] + adv));
    float den = p0;
    float4 s0v = *(const float4*)&g_h2[n * H2P];
    float4 s1v = *(const float4*)&g_h2[n * H2P + 4];
    float acc[CLS] = {p0*s0v.x, p0*s0v.y, p0*s0v.z, p0*s0v.w, p0*s1v.x, p0*s1v.y, p0*s1v.z};
    int beg = g_off[n], end = g_off[n + 1];

    int i = beg;
    for (; i + 4 <= end; i += 4) {
        int s0 = g_srcs[i], s1 = g_srcs[i + 1], s2 = g_srcs[i + 2], s3 = g_srcs[i + 3];
        float e0 = __ldg(&g_as2[s0]), e1 = __ldg(&g_as2[s1]);
        float e2 = __ldg(&g_as2[s2]), e3 = __ldg(&g_as2[s3]);
        float4 a0 = *(const float4*)&g_h2[s0 * H2P];
        float4 b0 = *(const float4*)&g_h2[s0 * H2P + 4];
        float4 a1 = *(const float4*)&g_h2[s1 * H2P];
        float4 b1v = *(const float4*)&g_h2[s1 * H2P + 4];
        float4 a2 = *(const float4*)&g_h2[s2 * H2P];
        float4 b2v = *(const float4*)&g_h2[s2 * H2P + 4];
        float4 a3 = *(const float4*)&g_h2[s3 * H2P];
        float4 b3v = *(const float4*)&g_h2[s3 * H2P + 4];
        float q0 = __expf(lrelu(e0 + adv));
        float q1 = __expf(lrelu(e1 + adv));
        float q2 = __expf(lrelu(e2 + adv));
        float q3 = __expf(lrelu(e3 + adv));
        den += (q0 + q1) + (q2 + q3);
        acc[0] = fmaf(q0, a0.x, acc[0]); acc[1] = fmaf(q0, a0.y, acc[1]);
        acc[2] = fmaf(q0, a0.z, acc[2]); acc[3] = fmaf(q0, a0.w, acc[3]);
        acc[4] = fmaf(q0, b0.x, acc[4]); acc[5] = fmaf(q0, b0.y, acc[5]);
        acc[6] = fmaf(q0, b0.z, acc[6]);
        acc[0] = fmaf(q1, a1.x, acc[0]); acc[1] = fmaf(q1, a1.y, acc[1]);
        acc[2] = fmaf(q1, a1.z, acc[2]); acc[3] = fmaf(q1, a1.w, acc[3]);
        acc[4] = fmaf(q1, b1v.x, acc[4]); acc[5] = fmaf(q1, b1v.y, acc[5]);
        acc[6] = fmaf(q1, b1v.z, acc[6]);
        acc[0] = fmaf(q2, a2.x, acc[0]); acc[1] = fmaf(q2, a2.y, acc[1]);
        acc[2] = fmaf(q2, a2.z, acc[2]); acc[3] = fmaf(q2, a2.w, acc[3]);
        acc[4] = fmaf(q2, b2v.x, acc[4]); acc[5] = fmaf(q2, b2v.y, acc[5]);
        acc[6] = fmaf(q2, b2v.z, acc[6]);
        acc[0] = fmaf(q3, a3.x, acc[0]); acc[1] = fmaf(q3, a3.y, acc[1]);
        acc[2] = fmaf(q3, a3.z, acc[2]); acc[3] = fmaf(q3, a3.w, acc[3]);
        acc[4] = fmaf(q3, b3v.x, acc[4]); acc[5] = fmaf(q3, b3v.y, acc[5]);
        acc[6] = fmaf(q3, b3v.z, acc[6]);
    }
    for (; i < end; ++i) {
        int s = g_srcs[i];
        float p = __expf(lrelu(__ldg(&g_as2[s]) + adv));
        den += p;
        float4 v0 = *(const float4*)&g_h2[s * H2P];
        float4 v1 = *(const float4*)&g_h2[s * H2P + 4];
        acc[0] = fmaf(p, v0.x, acc[0]);
        acc[1] = fmaf(p, v0.y, acc[1]);
        acc[2] = fmaf(p, v0.z, acc[2]);
        acc[3] = fmaf(p, v0.w, acc[3]);
        acc[4] = fmaf(p, v1.x, acc[4]);
        acc[5] = fmaf(p, v1.y, acc[5]);
        acc[6] = fmaf(p, v1.z, acc[6]);
    }
    float inv = 1.0f / den;
    float o[CLS];
    #pragma unroll
    for (int c = 0; c < CLS; c++) o[c] = fmaf(acc[c], inv, __ldg(&b2[c]));
    float mx = o[0];
    #pragma unroll
    for (int c = 1; c < CLS; c++) mx = fmaxf(mx, o[c]);
    float ssum = 0.f;
    #pragma unroll
    for (int c = 0; c < CLS; c++) ssum += __expf(o[c] - mx);
    float lse = __logf(ssum);
    #pragma unroll
    for (int c = 0; c < CLS; c++) out[n * CLS + c] = o[c] - mx - lse;
}

// ---------------- launch (CSR chain overlapped with GEMM on a side stream) ----------------
extern "C" void kernel_launch(void* const* d_in, const int* in_sizes, int n_in,
                              void* d_out, int out_size) {
    const float* x     = (const float*)d_in[0];
    const int*   ei    = (const int*)  d_in[1];
    const float* W1    = (const float*)d_in[2];
    const float* as1   = (const float*)d_in[3];
    const float* ad1   = (const float*)d_in[4];
    const float* b1    = (const float*)d_in[5];
    const float* W2    = (const float*)d_in[6];
    const float* as2   = (const float*)d_in[7];
    const float* ad2   = (const float*)d_in[8];
    const float* b2    = (const float*)d_in[9];
    float* out = (float*)d_out;

    int E = in_sizes[1] / 2;
    const int* src = ei;
    const int* dst = ei + E;
    int eb = (E + 255) / 256;

    static cudaStream_t sA = nullptr;
    static cudaEvent_t eFork = nullptr, eJoin = nullptr;
    if (sA == nullptr) {
        cudaStreamCreateWithFlags(&sA, cudaStreamNonBlocking);
        cudaEventCreateWithFlags(&eFork, cudaEventDisableTiming);
        cudaEventCreateWithFlags(&eJoin, cudaEventDisableTiming);
    }

    // fork: side stream joins the capture graph
    cudaEventRecord(eFork, 0);
    cudaStreamWaitEvent(sA, eFork, 0);

    // CSR chain on side stream, GEMM on main (launch 4 = ncu slot)
    k_zero_deg<<<(NN + 255) / 256, 256, 0, sA>>>();                 // 1
    k_hist<<<eb, 256, 0, sA>>>(dst, E);                             // 2
    k_scan1<<<NBLK, 1024, 0, sA>>>();                               // 3
    k_gemm1_tc<<<(NN + 127) / 128, 256>>>(x, W1, as1, ad1);         // 4 <- profiled
    k_scan2<<<1, 128, 0, sA>>>();                                   // 5
    k_scan3<<<(NN + 255) / 256, 256, 0, sA>>>();                    // 6
    k_scatter<<<eb, 256, 0, sA>>>(src, dst, E);                     // 7

    // join: main stream waits for CSR completion
    cudaEventRecord(eJoin, sA);
    cudaStreamWaitEvent(0, eJoin, 0);

    k_agg1<<<(NN * 32 + 255) / 256, 256>>>(b1, W2, as2, ad2);       // 8 (fused lin2)
    k_agg2<<<(NN + 255) / 256, 256>>>(b2, out);                     // 9 (thread per node)
}